// round 2
// baseline (speedup 1.0000x reference)
#include <cuda_runtime.h>

#define N_PATHS 65536
#define N_STEPS 512
#define TPB     128
#define WARPS   (TPB/32)
#define TILE    16

// ---- constants (match reference float32 semantics) ----
#define DT_F        (1.0f/252.0f)
#define SQRT_DT_F   0.06299407883487120f     // sqrt(1/252)
#define KAPPA_F     2.72f
#define THETA_F     (-3.5f)
#define SIGMA_P_F   0.85f
#define RHO_F       (-0.85f)
#define CS_F        (0.5267826876426369f * 0.06299407883487120f) // sqrt(1-rho^2)*sqrt_dt
#define R_F         0.0373f
#define LAMBDA_MAX_F 3.0f
#define LOG_V_MIN_F (-7.0f)
#define LOG_V_MAX_F 2.0f
#define INV_NSTEPS  (1.0f/512.0f)

__device__ __forceinline__ float fast_tanh(float x) {
    float y;
    asm("tanh.approx.f32 %0, %1;" : "=f"(y) : "f"(x));
    return y;
}

// JAX gelu(approximate=True): 0.5*x*(1+tanh(sqrt(2/pi)*(x+0.044715*x^3)))
__device__ __forceinline__ float gelu_t(float x) {
    float x2 = x * x;
    float u  = x * fmaf(0.0356774081363059f, x2, 0.7978845608028654f);
    return 0.5f * x * (1.0f + fast_tanh(u));
}

__global__ __launch_bounds__(TPB, 4)
void sde_kernel(const float* __restrict__ z1,  const float* __restrict__ z2,
                const float* __restrict__ W1,  const float* __restrict__ b1,
                const float* __restrict__ W2,  const float* __restrict__ b2,
                const float* __restrict__ W3,  const float* __restrict__ b3,
                const float* __restrict__ init_log_v,
                float* __restrict__ out)
{
    // weights (warp-uniform broadcast reads)
    __shared__ float sw0[32], sw1t[32], sb1[32], sb2[32], sw3[32];
    __shared__ __align__(16) float sW2[1024];
    __shared__ float sb3;
    // staging buffers, padded 17 (coprime with 32 banks -> conflict-free lane reads)
    __shared__ float sz1[WARPS][32][TILE + 1];
    __shared__ float sz2[WARPS][32][TILE + 1];
    __shared__ float sov[WARPS][32][TILE + 1];
    __shared__ float sos[WARPS][32][TILE + 1];

    const int tid = threadIdx.x;
    for (int i = tid; i < 1024; i += TPB) sW2[i] = W2[i];
    if (tid < 32) {
        sw0[tid]  = W1[2 * tid];
        sw1t[tid] = W1[2 * tid + 1];
        sb1[tid]  = b1[tid];
        sb2[tid]  = b2[tid];
        sw3[tid]  = W3[tid];
    }
    if (tid == 0) sb3 = b3[0];
    __syncthreads();

    const int w = tid >> 5;
    const int l = tid & 31;
    const int pbase = blockIdx.x * TPB + w * 32;   // first path of this warp

    const float* z1w = z1 + (size_t)pbase * N_STEPS;
    const float* z2w = z2 + (size_t)pbase * N_STEPS;
    float* out_lv = out;
    float* out_sp = out + (size_t)N_PATHS * N_STEPS;
    float* out_lq = out + 2 * (size_t)N_PATHS * N_STEPS;

    const float4* W2v = reinterpret_cast<const float4*>(sW2);

    float lv  = init_log_v[0];
    float ls  = 0.0f;
    float lsq = 0.0f;

    const int pl_lo = (l >> 2);        // 0..7
    const int so    = (l & 3) * 4;     // 0,4,8,12

    #pragma unroll 1
    for (int s0 = 0; s0 < N_STEPS; s0 += TILE) {
        __syncwarp();
        // ---- stage z (coalesced LDG.128 -> padded smem) ----
        #pragma unroll
        for (int it = 0; it < 4; it++) {
            int pl = it * 8 + pl_lo;
            float4 v1 = *reinterpret_cast<const float4*>(z1w + (size_t)pl * N_STEPS + s0 + so);
            float4 v2 = *reinterpret_cast<const float4*>(z2w + (size_t)pl * N_STEPS + s0 + so);
            sz1[w][pl][so]     = v1.x; sz1[w][pl][so + 1] = v1.y;
            sz1[w][pl][so + 2] = v1.z; sz1[w][pl][so + 3] = v1.w;
            sz2[w][pl][so]     = v2.x; sz2[w][pl][so + 1] = v2.y;
            sz2[w][pl][so + 2] = v2.z; sz2[w][pl][so + 3] = v2.w;
        }
        __syncwarp();

        // ---- 16 sequential SDE steps ----
        #pragma unroll 1
        for (int si = 0; si < TILE; si++) {
            const int s = s0 + si;
            const float t = (float)s * INV_NSTEPS;

            // layer 1: h1 = gelu(w0*lv + (w1*t + b1))
            float h1[32];
            #pragma unroll
            for (int k = 0; k < 32; k++) {
                float c1 = fmaf(sw1t[k], t, sb1[k]);
                h1[k] = gelu_t(fmaf(sw0[k], lv, c1));
            }

            // layer 2 fused with layer 3 reduction
            float r0 = 0.0f, r1 = 0.0f, r2 = 0.0f, r3 = 0.0f;
            #pragma unroll
            for (int j = 0; j < 32; j++) {
                float acc = sb2[j];
                #pragma unroll
                for (int k4 = 0; k4 < 8; k4++) {
                    float4 wv = W2v[j * 8 + k4];
                    acc = fmaf(wv.x, h1[4 * k4 + 0], acc);
                    acc = fmaf(wv.y, h1[4 * k4 + 1], acc);
                    acc = fmaf(wv.z, h1[4 * k4 + 2], acc);
                    acc = fmaf(wv.w, h1[4 * k4 + 3], acc);
                }
                float contrib = sw3[j] * gelu_t(acc);
                if ((j & 3) == 0) r0 += contrib;
                else if ((j & 3) == 1) r1 += contrib;
                else if ((j & 3) == 2) r2 += contrib;
                else r3 += contrib;
            }
            float raw = ((r0 + r1) + (r2 + r3)) + sb3;
            float lam = LAMBDA_MAX_F * tanhf(raw);   // accurate tanh for lambda

            // SDE update (pre-update lv used for ev/vol, as in reference)
            float z1s = sz1[w][l][si];
            float z2s = sz2[w][l][si];
            float dwv = SQRT_DT_F * z1s;
            float dws = fmaf(RHO_F, dwv, CS_F * z2s);

            float mu_p    = (KAPPA_F * (THETA_F - lv)) * DT_F;
            float drift_q = mu_p - (lam * SIGMA_P_F) * DT_F;
            float lv_next = lv + drift_q + SIGMA_P_F * dwv;
            lv_next = fminf(fmaxf(lv_next, LOG_V_MIN_F), LOG_V_MAX_F);

            float ev  = __expf(lv);
            float vol = sqrtf(fmaxf(ev, 1e-10f));
            float ls_next = ls + (R_F - 0.5f * ev) * DT_F + vol * dws;

            lsq = lsq + (lam * lam) * DT_F;

            sov[w][l][si] = lv_next;
            sos[w][l][si] = __expf(ls_next);

            lv = lv_next;
            ls = ls_next;
        }
        __syncwarp();

        // ---- flush outputs (padded smem -> coalesced STG.128) ----
        #pragma unroll
        for (int it = 0; it < 4; it++) {
            int pl = it * 8 + pl_lo;
            float4 ov, os;
            ov.x = sov[w][pl][so];     ov.y = sov[w][pl][so + 1];
            ov.z = sov[w][pl][so + 2]; ov.w = sov[w][pl][so + 3];
            os.x = sos[w][pl][so];     os.y = sos[w][pl][so + 1];
            os.z = sos[w][pl][so + 2]; os.w = sos[w][pl][so + 3];
            *reinterpret_cast<float4*>(out_lv + (size_t)(pbase + pl) * N_STEPS + s0 + so) = ov;
            *reinterpret_cast<float4*>(out_sp + (size_t)(pbase + pl) * N_STEPS + s0 + so) = os;
        }
    }

    out_lq[pbase + l] = lsq;
}

extern "C" void kernel_launch(void* const* d_in, const int* in_sizes, int n_in,
                              void* d_out, int out_size)
{
    (void)in_sizes; (void)n_in; (void)out_size;
    sde_kernel<<<N_PATHS / TPB, TPB>>>(
        (const float*)d_in[0], (const float*)d_in[1],
        (const float*)d_in[2], (const float*)d_in[3],
        (const float*)d_in[4], (const float*)d_in[5],
        (const float*)d_in[6], (const float*)d_in[7],
        (const float*)d_in[8],
        (float*)d_out);
}

// round 3
// speedup vs baseline: 10.5137x; 10.5137x over previous
#include <cuda_runtime.h>

#define N_PATHS 65536
#define N_STEPS 512
#define TPB     128
#define WARPS   (TPB/32)
#define TILE    16

// ---- constants (match reference float32 semantics) ----
#define DT_F        (1.0f/252.0f)
#define SQRT_DT_F   0.06299407883487120f     // sqrt(1/252)
#define KAPPA_F     2.72f
#define THETA_F     (-3.5f)
#define SIGMA_P_F   0.85f
#define RHO_F       (-0.85f)
#define CS_F        (0.5267826876426369f * 0.06299407883487120f) // sqrt(1-rho^2)*sqrt_dt
#define R_F         0.0373f
#define LAMBDA_MAX_F 3.0f
#define LOG_V_MIN_F (-7.0f)
#define LOG_V_MAX_F 2.0f
#define INV_NSTEPS  (1.0f/512.0f)

__device__ __forceinline__ float fast_tanh(float x) {
    float y;
    asm("tanh.approx.f32 %0, %1;" : "=f"(y) : "f"(x));
    return y;
}

// JAX gelu(approximate=True): 0.5*x*(1+tanh(sqrt(2/pi)*(x+0.044715*x^3)))
__device__ __forceinline__ float gelu_t(float x) {
    float x2 = x * x;
    float u  = x * fmaf(0.0356774081363059f, x2, 0.7978845608028654f);
    return 0.5f * x * (1.0f + fast_tanh(u));
}

__global__ __launch_bounds__(TPB, 3)
void sde_kernel(const float* __restrict__ z1,  const float* __restrict__ z2,
                const float* __restrict__ W1,  const float* __restrict__ b1,
                const float* __restrict__ W2,  const float* __restrict__ b2,
                const float* __restrict__ W3,  const float* __restrict__ b3,
                const float* __restrict__ init_log_v,
                float* __restrict__ out)
{
    // weights (warp-uniform broadcast reads)
    __shared__ float sw0[32], sw1t[32], sb1[32], sb2[32], sw3[32];
    __shared__ __align__(16) float sW2[1024];
    __shared__ float sb3;
    // staging buffers, padded 17 (coprime with 32 banks -> conflict-free lane reads)
    __shared__ float sz1[WARPS][32][TILE + 1];
    __shared__ float sz2[WARPS][32][TILE + 1];
    __shared__ float sov[WARPS][32][TILE + 1];
    __shared__ float sos[WARPS][32][TILE + 1];

    const int tid = threadIdx.x;
    for (int i = tid; i < 1024; i += TPB) sW2[i] = W2[i];
    if (tid < 32) {
        sw0[tid]  = W1[2 * tid];
        sw1t[tid] = W1[2 * tid + 1];
        sb1[tid]  = b1[tid];
        sb2[tid]  = b2[tid];
        sw3[tid]  = W3[tid];
    }
    if (tid == 0) sb3 = b3[0];
    __syncthreads();

    const int w = tid >> 5;
    const int l = tid & 31;
    const int pbase = blockIdx.x * TPB + w * 32;   // first path of this warp

    const float* z1w = z1 + (size_t)pbase * N_STEPS;
    const float* z2w = z2 + (size_t)pbase * N_STEPS;
    float* out_lv = out;
    float* out_sp = out + (size_t)N_PATHS * N_STEPS;
    float* out_lq = out + 2 * (size_t)N_PATHS * N_STEPS;

    const float4* W2v = reinterpret_cast<const float4*>(sW2);

    float lv  = init_log_v[0];
    float ls  = 0.0f;
    float lsq = 0.0f;

    const int pl_lo = (l >> 2);        // 0..7
    const int so    = (l & 3) * 4;     // 0,4,8,12

    #pragma unroll 1
    for (int s0 = 0; s0 < N_STEPS; s0 += TILE) {
        __syncwarp();
        // ---- stage z (coalesced LDG.128 -> padded smem) ----
        #pragma unroll
        for (int it = 0; it < 4; it++) {
            int pl = it * 8 + pl_lo;
            float4 v1 = *reinterpret_cast<const float4*>(z1w + (size_t)pl * N_STEPS + s0 + so);
            float4 v2 = *reinterpret_cast<const float4*>(z2w + (size_t)pl * N_STEPS + s0 + so);
            sz1[w][pl][so]     = v1.x; sz1[w][pl][so + 1] = v1.y;
            sz1[w][pl][so + 2] = v1.z; sz1[w][pl][so + 3] = v1.w;
            sz2[w][pl][so]     = v2.x; sz2[w][pl][so + 1] = v2.y;
            sz2[w][pl][so + 2] = v2.z; sz2[w][pl][so + 3] = v2.w;
        }
        __syncwarp();

        // ---- 16 sequential SDE steps ----
        #pragma unroll 1
        for (int si = 0; si < TILE; si++) {
            const int s = s0 + si;
            const float t = (float)s * INV_NSTEPS;

            // layer 1: h1 = gelu(w0*lv + (w1*t + b1))
            float h1[32];
            #pragma unroll
            for (int k = 0; k < 32; k++) {
                float c1 = fmaf(sw1t[k], t, sb1[k]);
                h1[k] = gelu_t(fmaf(sw0[k], lv, c1));
            }

            // layer 2 fused with layer 3 reduction.
            // 8 groups of 4 output neurons; unroll 1 keeps the live set small
            // (4 acc + 16 weight regs) so nothing spills. ILP = 4 chains.
            float red = 0.0f;
            #pragma unroll 1
            for (int jg = 0; jg < 8; jg++) {
                const int j0 = jg * 4;
                float a0 = sb2[j0 + 0];
                float a1 = sb2[j0 + 1];
                float a2 = sb2[j0 + 2];
                float a3 = sb2[j0 + 3];
                #pragma unroll
                for (int k4 = 0; k4 < 8; k4++) {
                    float hx = h1[4 * k4 + 0];
                    float hy = h1[4 * k4 + 1];
                    float hz = h1[4 * k4 + 2];
                    float hw = h1[4 * k4 + 3];
                    float4 w0v = W2v[(j0 + 0) * 8 + k4];
                    float4 w1v = W2v[(j0 + 1) * 8 + k4];
                    float4 w2v = W2v[(j0 + 2) * 8 + k4];
                    float4 w3v = W2v[(j0 + 3) * 8 + k4];
                    a0 = fmaf(w0v.x, hx, a0); a0 = fmaf(w0v.y, hy, a0);
                    a0 = fmaf(w0v.z, hz, a0); a0 = fmaf(w0v.w, hw, a0);
                    a1 = fmaf(w1v.x, hx, a1); a1 = fmaf(w1v.y, hy, a1);
                    a1 = fmaf(w1v.z, hz, a1); a1 = fmaf(w1v.w, hw, a1);
                    a2 = fmaf(w2v.x, hx, a2); a2 = fmaf(w2v.y, hy, a2);
                    a2 = fmaf(w2v.z, hz, a2); a2 = fmaf(w2v.w, hw, a2);
                    a3 = fmaf(w3v.x, hx, a3); a3 = fmaf(w3v.y, hy, a3);
                    a3 = fmaf(w3v.z, hz, a3); a3 = fmaf(w3v.w, hw, a3);
                }
                float c0 = sw3[j0 + 0] * gelu_t(a0);
                float c1 = sw3[j0 + 1] * gelu_t(a1);
                float c2 = sw3[j0 + 2] * gelu_t(a2);
                float c3 = sw3[j0 + 3] * gelu_t(a3);
                red += (c0 + c1) + (c2 + c3);
            }
            float raw = red + sb3;
            float lam = LAMBDA_MAX_F * tanhf(raw);   // accurate tanh for lambda

            // SDE update (pre-update lv used for ev/vol, as in reference)
            float z1s = sz1[w][l][si];
            float z2s = sz2[w][l][si];
            float dwv = SQRT_DT_F * z1s;
            float dws = fmaf(RHO_F, dwv, CS_F * z2s);

            float mu_p    = (KAPPA_F * (THETA_F - lv)) * DT_F;
            float drift_q = mu_p - (lam * SIGMA_P_F) * DT_F;
            float lv_next = lv + drift_q + SIGMA_P_F * dwv;
            lv_next = fminf(fmaxf(lv_next, LOG_V_MIN_F), LOG_V_MAX_F);

            float ev  = __expf(lv);
            float vol = sqrtf(fmaxf(ev, 1e-10f));
            float ls_next = ls + (R_F - 0.5f * ev) * DT_F + vol * dws;

            lsq = lsq + (lam * lam) * DT_F;

            sov[w][l][si] = lv_next;
            sos[w][l][si] = __expf(ls_next);

            lv = lv_next;
            ls = ls_next;
        }
        __syncwarp();

        // ---- flush outputs (padded smem -> coalesced STG.128) ----
        #pragma unroll
        for (int it = 0; it < 4; it++) {
            int pl = it * 8 + pl_lo;
            float4 ov, os;
            ov.x = sov[w][pl][so];     ov.y = sov[w][pl][so + 1];
            ov.z = sov[w][pl][so + 2]; ov.w = sov[w][pl][so + 3];
            os.x = sos[w][pl][so];     os.y = sos[w][pl][so + 1];
            os.z = sos[w][pl][so + 2]; os.w = sos[w][pl][so + 3];
            *reinterpret_cast<float4*>(out_lv + (size_t)(pbase + pl) * N_STEPS + s0 + so) = ov;
            *reinterpret_cast<float4*>(out_sp + (size_t)(pbase + pl) * N_STEPS + s0 + so) = os;
        }
    }

    out_lq[pbase + l] = lsq;
}

extern "C" void kernel_launch(void* const* d_in, const int* in_sizes, int n_in,
                              void* d_out, int out_size)
{
    (void)in_sizes; (void)n_in; (void)out_size;
    sde_kernel<<<N_PATHS / TPB, TPB>>>(
        (const float*)d_in[0], (const float*)d_in[1],
        (const float*)d_in[2], (const float*)d_in[3],
        (const float*)d_in[4], (const float*)d_in[5],
        (const float*)d_in[6], (const float*)d_in[7],
        (const float*)d_in[8],
        (float*)d_out);
}

// round 4
// speedup vs baseline: 16.0762x; 1.5291x over previous
#include <cuda_runtime.h>

#define N_PATHS 65536
#define N_STEPS 512
#define TPB     64
#define WARPS   (TPB/32)     // 2
#define PPT     2            // paths per thread (f32x2 lanes)
#define TILE    16

// ---- constants (match reference float32 semantics) ----
#define DT_F        (1.0f/252.0f)
#define SQRT_DT_F   0.06299407883487120f     // sqrt(1/252)
#define KAPPA_F     2.72f
#define THETA_F     (-3.5f)
#define SIGMA_P_F   0.85f
#define RHO_F       (-0.85f)
#define CS_F        (0.5267826876426369f * 0.06299407883487120f) // sqrt(1-rho^2)*sqrt_dt
#define R_F         0.0373f
#define LAMBDA_MAX_F 3.0f
#define LOG_V_MIN_F (-7.0f)
#define LOG_V_MAX_F 2.0f
#define INV_NSTEPS  (1.0f/512.0f)

typedef unsigned long long ull;

// ---- packed f32x2 helpers (Blackwell: fma.rn.f32x2 etc., ptxas won't auto-fuse) ----
__device__ __forceinline__ ull pack2(float a, float b) {
    ull r; asm("mov.b64 %0, {%1, %2};" : "=l"(r) : "f"(a), "f"(b)); return r;
}
__device__ __forceinline__ void unpack2(ull v, float& a, float& b) {
    asm("mov.b64 {%0, %1}, %2;" : "=f"(a), "=f"(b) : "l"(v));
}
__device__ __forceinline__ ull fma2(ull a, ull b, ull c) {
    ull d; asm("fma.rn.f32x2 %0, %1, %2, %3;" : "=l"(d) : "l"(a), "l"(b), "l"(c)); return d;
}
__device__ __forceinline__ ull mul2(ull a, ull b) {
    ull d; asm("mul.rn.f32x2 %0, %1, %2;" : "=l"(d) : "l"(a), "l"(b)); return d;
}

__device__ __forceinline__ float fast_tanh(float x) {
    float y;
    asm("tanh.approx.f32 %0, %1;" : "=f"(y) : "f"(x));
    return y;
}

// JAX gelu(approximate=True) on an f32x2 pair: 0.5*x*(1+tanh(c*(x+0.044715*x^3)))
__device__ __forceinline__ ull gelu2(ull x, ull GA, ull GB, ull GH) {
    ull x2 = mul2(x, x);
    ull u  = mul2(x, fma2(GA, x2, GB));
    float ulo, uhi; unpack2(u, ulo, uhi);
    float tl = fast_tanh(ulo) + 1.0f;
    float th = fast_tanh(uhi) + 1.0f;
    ull tp = pack2(tl, th);
    return mul2(mul2(GH, x), tp);
}

// scalar SDE update per path (identical numerics to the validated R3 kernel)
__device__ __forceinline__ void sde_step(float lam, float z1s, float z2s,
                                         float& lv, float& ls, float& lsq,
                                         float& o_lv, float& o_sp)
{
    float dwv = SQRT_DT_F * z1s;
    float dws = fmaf(RHO_F, dwv, CS_F * z2s);
    float mu_p    = (KAPPA_F * (THETA_F - lv)) * DT_F;
    float drift_q = mu_p - (lam * SIGMA_P_F) * DT_F;
    float lv_next = lv + drift_q + SIGMA_P_F * dwv;
    lv_next = fminf(fmaxf(lv_next, LOG_V_MIN_F), LOG_V_MAX_F);
    float ev  = __expf(lv);
    float vol = sqrtf(fmaxf(ev, 1e-10f));
    float ls_next = ls + (R_F - 0.5f * ev) * DT_F + vol * dws;
    lsq = fmaf(lam * lam, DT_F, lsq);
    o_lv = lv_next;
    o_sp = __expf(ls_next);
    lv = lv_next;
    ls = ls_next;
}

__global__ __launch_bounds__(TPB, 4)
void sde_kernel(const float* __restrict__ z1,  const float* __restrict__ z2,
                const float* __restrict__ W1,  const float* __restrict__ b1,
                const float* __restrict__ W2,  const float* __restrict__ b2,
                const float* __restrict__ W3,  const float* __restrict__ b3,
                const float* __restrict__ init_log_v,
                float* __restrict__ out)
{
    // weights (warp-uniform broadcast reads); dup-pairs prebuilt for f32x2 operands
    __shared__ float sw1t[32], sb1[32];
    __shared__ ull   sw0d[32], sb2d[32], sw3d[32];
    __shared__ __align__(16) float sW2[1024];
    __shared__ float sb3s;
    // staging buffers (z in, outputs overwrite in place), 17-pad = conflict-free
    __shared__ float sza[WARPS][64][TILE + 1];   // z1 -> log_v out
    __shared__ float szb[WARPS][64][TILE + 1];   // z2 -> spot  out

    const int tid = threadIdx.x;
    for (int i = tid; i < 1024; i += TPB) sW2[i] = W2[i];
    if (tid < 32) {
        float w0 = W1[2 * tid];
        sw0d[tid] = pack2(w0, w0);
        sw1t[tid] = W1[2 * tid + 1];
        sb1[tid]  = b1[tid];
        float bb = b2[tid];
        sb2d[tid] = pack2(bb, bb);
        float w3 = W3[tid];
        sw3d[tid] = pack2(w3, w3);
    }
    if (tid == 0) sb3s = b3[0];
    __syncthreads();

    const int w = tid >> 5;
    const int l = tid & 31;
    const int pbase = blockIdx.x * (TPB * PPT) + w * 64;   // 64 paths per warp
    // thread handles paths (pbase + l) [lane A] and (pbase + l + 32) [lane B]

    const float* z1w = z1 + (size_t)pbase * N_STEPS;
    const float* z2w = z2 + (size_t)pbase * N_STEPS;
    float* out_lv = out;
    float* out_sp = out + (size_t)N_PATHS * N_STEPS;
    float* out_lq = out + 2 * (size_t)N_PATHS * N_STEPS;

    const float4* W2v = reinterpret_cast<const float4*>(sW2);

    const ull GA = pack2(0.0356774081363059f, 0.0356774081363059f);
    const ull GB = pack2(0.7978845608028654f, 0.7978845608028654f);
    const ull GH = pack2(0.5f, 0.5f);

    float lvA = init_log_v[0], lvB = lvA;
    float lsA = 0.0f, lsB = 0.0f;
    float lsqA = 0.0f, lsqB = 0.0f;

    #pragma unroll 1
    for (int s0 = 0; s0 < N_STEPS; s0 += TILE) {
        __syncwarp();
        // ---- stage z (coalesced LDG.128 -> padded smem), 64 rows x 16 cols ----
        #pragma unroll
        for (int i = 0; i < 8; i++) {
            int qi  = l + 32 * i;          // 0..255 quads
            int row = qi >> 2;
            int c0  = (qi & 3) * 4;
            float4 v1 = *reinterpret_cast<const float4*>(z1w + (size_t)row * N_STEPS + s0 + c0);
            float4 v2 = *reinterpret_cast<const float4*>(z2w + (size_t)row * N_STEPS + s0 + c0);
            sza[w][row][c0]     = v1.x; sza[w][row][c0 + 1] = v1.y;
            sza[w][row][c0 + 2] = v1.z; sza[w][row][c0 + 3] = v1.w;
            szb[w][row][c0]     = v2.x; szb[w][row][c0 + 1] = v2.y;
            szb[w][row][c0 + 2] = v2.z; szb[w][row][c0 + 3] = v2.w;
        }
        __syncwarp();

        // ---- 16 sequential SDE steps, 2 paths per thread via f32x2 ----
        #pragma unroll 1
        for (int si = 0; si < TILE; si++) {
            const int s = s0 + si;
            const float t = (float)s * INV_NSTEPS;
            const ull lvp = pack2(lvA, lvB);

            // layer 1: h1 = gelu(w0*lv + (w1*t + b1)), paired over paths
            ull h1[32];
            #pragma unroll
            for (int k = 0; k < 32; k++) {
                float c1 = fmaf(sw1t[k], t, sb1[k]);       // uniform across pair
                ull arg = fma2(sw0d[k], lvp, pack2(c1, c1));
                h1[k] = gelu2(arg, GA, GB, GH);
            }

            // layer 2 + layer 3 reduction. 8 groups of 4 neurons (unroll 1 ->
            // small live set). Each weight: 1 dup-pack (alu) + 1 FFMA2 serving
            // both paths. Weight quad loads shared across the pair.
            ull red0 = pack2(0.0f, 0.0f);
            ull red1 = pack2(0.0f, 0.0f);
            #pragma unroll 1
            for (int jg = 0; jg < 8; jg++) {
                const int j0 = jg * 4;
                ull a0 = sb2d[j0 + 0];
                ull a1 = sb2d[j0 + 1];
                ull a2 = sb2d[j0 + 2];
                ull a3 = sb2d[j0 + 3];
                #pragma unroll
                for (int k4 = 0; k4 < 8; k4++) {
                    ull h0 = h1[4 * k4 + 0];
                    ull hA = h1[4 * k4 + 1];
                    ull hB = h1[4 * k4 + 2];
                    ull hC = h1[4 * k4 + 3];
                    float4 q0 = W2v[(j0 + 0) * 8 + k4];
                    float4 q1 = W2v[(j0 + 1) * 8 + k4];
                    float4 q2 = W2v[(j0 + 2) * 8 + k4];
                    float4 q3 = W2v[(j0 + 3) * 8 + k4];
                    a0 = fma2(pack2(q0.x, q0.x), h0, a0);
                    a0 = fma2(pack2(q0.y, q0.y), hA, a0);
                    a0 = fma2(pack2(q0.z, q0.z), hB, a0);
                    a0 = fma2(pack2(q0.w, q0.w), hC, a0);
                    a1 = fma2(pack2(q1.x, q1.x), h0, a1);
                    a1 = fma2(pack2(q1.y, q1.y), hA, a1);
                    a1 = fma2(pack2(q1.z, q1.z), hB, a1);
                    a1 = fma2(pack2(q1.w, q1.w), hC, a1);
                    a2 = fma2(pack2(q2.x, q2.x), h0, a2);
                    a2 = fma2(pack2(q2.y, q2.y), hA, a2);
                    a2 = fma2(pack2(q2.z, q2.z), hB, a2);
                    a2 = fma2(pack2(q2.w, q2.w), hC, a2);
                    a3 = fma2(pack2(q3.x, q3.x), h0, a3);
                    a3 = fma2(pack2(q3.y, q3.y), hA, a3);
                    a3 = fma2(pack2(q3.z, q3.z), hB, a3);
                    a3 = fma2(pack2(q3.w, q3.w), hC, a3);
                }
                red0 = fma2(sw3d[j0 + 0], gelu2(a0, GA, GB, GH), red0);
                red1 = fma2(sw3d[j0 + 1], gelu2(a1, GA, GB, GH), red1);
                red0 = fma2(sw3d[j0 + 2], gelu2(a2, GA, GB, GH), red0);
                red1 = fma2(sw3d[j0 + 3], gelu2(a3, GA, GB, GH), red1);
            }
            float rA0, rB0, rA1, rB1;
            unpack2(red0, rA0, rB0);
            unpack2(red1, rA1, rB1);
            float rawA = (rA0 + rA1) + sb3s;
            float rawB = (rB0 + rB1) + sb3s;
            float lamA = LAMBDA_MAX_F * tanhf(rawA);   // accurate tanh for lambda
            float lamB = LAMBDA_MAX_F * tanhf(rawB);

            // SDE updates (scalar per path; z consumed, outputs overwrite slot)
            float zA1 = sza[w][l][si],      zA2 = szb[w][l][si];
            float zB1 = sza[w][l + 32][si], zB2 = szb[w][l + 32][si];
            float oLvA, oSpA, oLvB, oSpB;
            sde_step(lamA, zA1, zA2, lvA, lsA, lsqA, oLvA, oSpA);
            sde_step(lamB, zB1, zB2, lvB, lsB, lsqB, oLvB, oSpB);
            sza[w][l][si]      = oLvA;  szb[w][l][si]      = oSpA;
            sza[w][l + 32][si] = oLvB;  szb[w][l + 32][si] = oSpB;
        }
        __syncwarp();

        // ---- flush outputs (padded smem -> coalesced STG.128) ----
        #pragma unroll
        for (int i = 0; i < 8; i++) {
            int qi  = l + 32 * i;
            int row = qi >> 2;
            int c0  = (qi & 3) * 4;
            float4 ov, os;
            ov.x = sza[w][row][c0];     ov.y = sza[w][row][c0 + 1];
            ov.z = sza[w][row][c0 + 2]; ov.w = sza[w][row][c0 + 3];
            os.x = szb[w][row][c0];     os.y = szb[w][row][c0 + 1];
            os.z = szb[w][row][c0 + 2]; os.w = szb[w][row][c0 + 3];
            *reinterpret_cast<float4*>(out_lv + (size_t)(pbase + row) * N_STEPS + s0 + c0) = ov;
            *reinterpret_cast<float4*>(out_sp + (size_t)(pbase + row) * N_STEPS + s0 + c0) = os;
        }
    }

    out_lq[pbase + l]      = lsqA;
    out_lq[pbase + l + 32] = lsqB;
}

extern "C" void kernel_launch(void* const* d_in, const int* in_sizes, int n_in,
                              void* d_out, int out_size)
{
    (void)in_sizes; (void)n_in; (void)out_size;
    sde_kernel<<<N_PATHS / (TPB * PPT), TPB>>>(
        (const float*)d_in[0], (const float*)d_in[1],
        (const float*)d_in[2], (const float*)d_in[3],
        (const float*)d_in[4], (const float*)d_in[5],
        (const float*)d_in[6], (const float*)d_in[7],
        (const float*)d_in[8],
        (float*)d_out);
}